// round 5
// baseline (speedup 1.0000x reference)
#include <cuda_runtime.h>

#define BATCH 4096
#define TSEQ  20
#define INSZ  512
#define HSZ   512
#define RNK   20
#define G4    2048
#define NB    64          // batch rows per block
#define JT    128         // j columns per block
#define HSTRD 130         // ht row stride

// Scratch (no allocations allowed -> device globals)
__device__ float g_u[BATCH * TSEQ * RNK];      // [b][t][r] input projection
__device__ float g_c[BATCH * HSZ];             // cell state, tiled [(bc*4+jt)][bb][jjl]
__device__ float g_hu[2][4 * BATCH * RNK];     // [parity][jt][b][r] h@whh_a partials

typedef unsigned long long ull;

__device__ __forceinline__ void ffma2(ull &d, ull a, ull b) {
    asm("fma.rn.f32x2 %0, %1, %2, %0;" : "+l"(d) : "l"(a), "l"(b));
}
__device__ __forceinline__ ull add2(ull a, ull b) {
    ull d; asm("add.rn.f32x2 %0, %1, %2;" : "=l"(d) : "l"(a), "l"(b)); return d;
}
__device__ __forceinline__ ull pack2(float x, float y) {
    ull r; asm("mov.b64 %0, {%1, %2};" : "=l"(r) : "f"(x), "f"(y)); return r;
}
__device__ __forceinline__ float2 unpack2(ull v) {
    float2 f; asm("mov.b64 {%0, %1}, %2;" : "=f"(f.x), "=f"(f.y) : "l"(v)); return f;
}
__device__ __forceinline__ float tanha(float x) {
    float y; asm("tanh.approx.f32 %0, %1;" : "=f"(y) : "f"(x)); return y;
}
__device__ __forceinline__ float siga(float x) {
    return fmaf(tanha(0.5f * x), 0.5f, 0.5f);
}

// ---------------------------------------------------------------------------
__global__ __launch_bounds__(256) void kPre(const float* __restrict__ x,
                                            const float* __restrict__ wa) {
    __shared__ __align__(16) float was[INSZ * RNK];
    for (int idx = threadIdx.x; idx < INSZ * RNK; idx += blockDim.x) was[idx] = wa[idx];
    __syncthreads();

    const int row = blockIdx.x * blockDim.x + threadIdx.x;
    const float4* xr = reinterpret_cast<const float4*>(x + (long)row * INSZ);

    ull acc[10];
#pragma unroll
    for (int q = 0; q < 10; q++) acc[q] = 0ull;

#pragma unroll 4
    for (int k4 = 0; k4 < INSZ / 4; k4++) {
        float4 xv = xr[k4];
#pragma unroll
        for (int i = 0; i < 4; i++) {
            float kv = (i == 0) ? xv.x : (i == 1) ? xv.y : (i == 2) ? xv.z : xv.w;
            ull ks = pack2(kv, kv);
            const ulonglong2* w2 = reinterpret_cast<const ulonglong2*>(was + (k4 * 4 + i) * RNK);
#pragma unroll
            for (int q = 0; q < 5; q++) {
                ulonglong2 wv = w2[q];
                ffma2(acc[2 * q + 0], ks, wv.x);
                ffma2(acc[2 * q + 1], ks, wv.y);
            }
        }
    }
    float* up = g_u + (long)row * RNK;
#pragma unroll
    for (int q = 0; q < 10; q++) {
        float2 f = unpack2(acc[q]);
        up[2 * q + 0] = f.x;
        up[2 * q + 1] = f.y;
    }
}

// ---------------------------------------------------------------------------
// smem partition (floats)
#define WT_OFF   0
#define WT_SZ    (40 * 512)                 // wT[k][jjl*4+gate]; reused for hu partials
#define VS_OFF   (WT_OFF + WT_SZ)
#define VS_SZ    (40 * NB * 2)              // vsplat[k][bb] as ull
#define BS_OFF   (VS_OFF + VS_SZ)
#define BS_SZ    512                        // bias [jjl*4+gate]
#define HT_OFF   (BS_OFF + BS_SZ)
#define HT_SZ    (NB * HSTRD)
#define WA_OFF   (HT_OFF + HT_SZ)
#define WA_SZ    (JT * RNK)                 // wa[j][r]
#define SMEM_FLOATS (WA_OFF + WA_SZ)

__global__ __launch_bounds__(512, 1) void kStep(
    const float* __restrict__ wih_b, const float* __restrict__ b_ih,
    const float* __restrict__ whh_a, const float* __restrict__ whh_b,
    const float* __restrict__ b_hh,
    float* __restrict__ out, int t,
    float* __restrict__ hdst, float* __restrict__ cdst) {

    extern __shared__ __align__(16) float sm[];
    float* wT  = sm + WT_OFF;
    ull*   vsp = reinterpret_cast<ull*>(sm + VS_OFF);
    float* bs  = sm + BS_OFF;
    float* ht  = sm + HT_OFF;
    float* wa  = sm + WA_OFF;

    const int tid = threadIdx.x;
    const int jt = blockIdx.x, bc = blockIdx.y;
    const int j0 = jt * JT, b0 = bc * NB;
    const int mtile = tid & 63, ntile = tid >> 6;     // 64 x 8 thread grid
    const int jjl0 = mtile * 2, bb0 = ntile * 8;
    const long ctile = (long)(bc * 4 + jt) * (NB * JT);

    const float* rd = g_hu[t & 1];
    float*       wr = g_hu[(t + 1) & 1];

    // ---- prefetch this thread's c cells early (t==0: zeros, no read) ----
    float2 creg[8];
    if (t > 0) {
#pragma unroll
        for (int n = 0; n < 8; n++)
            creg[n] = *reinterpret_cast<const float2*>(g_c + ctile + (bb0 + n) * JT + jjl0);
    } else {
#pragma unroll
        for (int n = 0; n < 8; n++) creg[n] = make_float2(0.f, 0.f);
    }

    // ---- stage wT[k][jjl*4+gate]: coalesced LDG.32, conflict-free STS.128 ----
    {
        const int sj = tid & 127, sk = tid >> 7;      // jjl, k-phase
#pragma unroll
        for (int it = 0; it < 10; it++) {
            int r = it * 4 + sk;
            const float* src = (r < RNK) ? (wih_b + r * G4 + j0)
                                         : (whh_b + (r - RNK) * G4 + j0);
            float4 v;
            v.x = src[0 * 512 + sj];
            v.y = src[1 * 512 + sj];
            v.z = src[2 * 512 + sj];
            v.w = src[3 * 512 + sj];
            *reinterpret_cast<float4*>(wT + r * 512 + sj * 4) = v;
        }
    }
    // ---- bias [jjl*4+gate] ----
    {
        int jjl = tid >> 2, gate = tid & 3;
        int col = gate * 512 + j0 + jjl;
        bs[tid] = b_ih[col] + b_hh[col];
    }
    // ---- wa[j][r] = whh_a[(j0+j)][r]: straight float4 copy ----
    for (int idx = tid; idx < (JT * RNK) / 4; idx += 512)
        reinterpret_cast<float4*>(wa)[idx] =
            reinterpret_cast<const float4*>(whh_a + j0 * RNK)[idx];
    // ---- v = [u_t | sum of 4 hu partials], pre-splatted ----
    for (int idx = tid; idx < NB * 40; idx += 512) {
        int bb = idx / 40, r = idx % 40;
        int b = b0 + bb;
        float v;
        if (r < RNK) {
            v = g_u[b * (TSEQ * RNK) + t * RNK + r];
        } else if (t > 0) {
            int off = b * RNK + (r - RNK);
            v = rd[off] + rd[BATCH * RNK + off]
              + rd[2 * BATCH * RNK + off] + rd[3 * BATCH * RNK + off];
        } else {
            v = 0.f;
        }
        vsp[r * NB + bb] = pack2(v, v);
    }
    __syncthreads();

    // ---- main GEMM: acc[mp][n]; mp: (i,f)j0 (g,o)j0 (i,f)j1 (g,o)j1 ----
    ull acc[4][8];
    {
        const ulonglong2* bp = reinterpret_cast<const ulonglong2*>(bs + jjl0 * 4);
        ulonglong2 bA = bp[0], bB = bp[1];
#pragma unroll
        for (int n = 0; n < 8; n++) {
            acc[0][n] = bA.x; acc[1][n] = bA.y;
            acc[2][n] = bB.x; acc[3][n] = bB.y;
        }
    }

#pragma unroll 8
    for (int k = 0; k < 40; k++) {
        const ulonglong2* wrow = reinterpret_cast<const ulonglong2*>(wT + k * 512 + jjl0 * 4);
        ulonglong2 wA = wrow[0], wB = wrow[1];
        const ulonglong2* vrow = reinterpret_cast<const ulonglong2*>(vsp + k * NB + bb0);
        ulonglong2 v0 = vrow[0], v1 = vrow[1], v2 = vrow[2], v3 = vrow[3];
        ull vn[8] = {v0.x, v0.y, v1.x, v1.y, v2.x, v2.y, v3.x, v3.y};
#pragma unroll
        for (int n = 0; n < 8; n++) {
            ffma2(acc[0][n], wA.x, vn[n]);
            ffma2(acc[1][n], wA.y, vn[n]);
            ffma2(acc[2][n], wB.x, vn[n]);
            ffma2(acc[3][n], wB.y, vn[n]);
        }
    }

    // ---- epilogue: full cell update in-thread (MUFU.TANH activations) ----
    const bool last = (hdst != nullptr);
#pragma unroll
    for (int n = 0; n < 8; n++) {
        int bb = bb0 + n;
        int b = b0 + bb;
        float2 if0 = unpack2(acc[0][n]);   // i, f of jjl0
        float2 go0 = unpack2(acc[1][n]);   // g, o of jjl0
        float2 if1 = unpack2(acc[2][n]);
        float2 go1 = unpack2(acc[3][n]);
        float2 cold = creg[n];
        float2 cc, hh;
        cc.x = fmaf(siga(if0.y), cold.x, siga(if0.x) * tanha(go0.x));
        hh.x = siga(go0.y) * tanha(cc.x);
        cc.y = fmaf(siga(if1.y), cold.y, siga(if1.x) * tanha(go1.x));
        hh.y = siga(go1.y) * tanha(cc.y);
        *reinterpret_cast<float2*>(g_c + ctile + bb * JT + jjl0) = cc;
        *reinterpret_cast<float2*>(out + ((long)b * TSEQ + t) * HSZ + j0 + jjl0) = hh;
        *reinterpret_cast<float2*>(ht + bb * HSTRD + jjl0) = hh;
        if (last) {
            *reinterpret_cast<float2*>(hdst + (long)b * HSZ + j0 + jjl0) = hh;
            *reinterpret_cast<float2*>(cdst + (long)b * HSZ + j0 + jjl0) = cc;
        }
    }
    __syncthreads();

    // ---- hu partials: thread (js, bb) accumulates ALL 20 r over 16 j ----
    {
        ull* part = reinterpret_cast<ull*>(wT);
        const int js = tid >> 6, bb = tid & 63;
        ull a10[10];
#pragma unroll
        for (int rp = 0; rp < 10; rp++) a10[rp] = 0ull;
        const int jbeg = js * 16;
#pragma unroll
        for (int jj = 0; jj < 16; jj++) {
            int j = jbeg + jj;
            float hv = ht[bb * HSTRD + j];
            ull hs2 = pack2(hv, hv);
            const ulonglong2* war = reinterpret_cast<const ulonglong2*>(wa + j * RNK);
            ulonglong2 w0 = war[0], w1 = war[1], w2 = war[2], w3 = war[3], w4 = war[4];
            ffma2(a10[0], hs2, w0.x); ffma2(a10[1], hs2, w0.y);
            ffma2(a10[2], hs2, w1.x); ffma2(a10[3], hs2, w1.y);
            ffma2(a10[4], hs2, w2.x); ffma2(a10[5], hs2, w2.y);
            ffma2(a10[6], hs2, w3.x); ffma2(a10[7], hs2, w3.y);
            ffma2(a10[8], hs2, w4.x); ffma2(a10[9], hs2, w4.y);
        }
#pragma unroll
        for (int rp = 0; rp < 10; rp++)
            part[(rp * 8 + js) * 64 + bb] = a10[rp];
    }
    __syncthreads();

    // ---- reduce 8 jslices, write hu to global ----
    {
        const ull* part = reinterpret_cast<const ull*>(wT);
#pragma unroll
        for (int o = tid; o < NB * 10; o += 512) {
            int bb = o & 63, rp = o >> 6;
            ull s = part[(rp * 8 + 0) * 64 + bb];
#pragma unroll
            for (int js = 1; js < 8; js++)
                s = add2(s, part[(rp * 8 + js) * 64 + bb]);
            float2 f = unpack2(s);
            *reinterpret_cast<float2*>(
                wr + jt * (BATCH * RNK) + (b0 + bb) * RNK + 2 * rp) = f;
        }
    }
}

// ---------------------------------------------------------------------------
extern "C" void kernel_launch(void* const* d_in, const int* in_sizes, int n_in,
                              void* d_out, int out_size) {
    const float* x     = (const float*)d_in[0];
    const float* wih_a = (const float*)d_in[1];
    const float* wih_b = (const float*)d_in[2];
    const float* b_ih  = (const float*)d_in[3];
    const float* whh_a = (const float*)d_in[4];
    const float* whh_b = (const float*)d_in[5];
    const float* b_hh  = (const float*)d_in[6];
    float* out = (float*)d_out;

    const long BTH = (long)BATCH * TSEQ * HSZ;
    float* hdst = nullptr;
    float* cdst = nullptr;
    if ((long)out_size >= BTH + 2L * BATCH * HSZ) {
        hdst = out + BTH;
        cdst = hdst + (long)BATCH * HSZ;
    }

    cudaFuncSetAttribute(kStep, cudaFuncAttributeMaxDynamicSharedMemorySize,
                         SMEM_FLOATS * 4);

    kPre<<<(BATCH * TSEQ) / 256, 256>>>(x, wih_a);
    for (int t = 0; t < TSEQ; t++) {
        bool lastT = (t == TSEQ - 1);
        kStep<<<dim3(4, 64), 512, SMEM_FLOATS * 4>>>(
            wih_b, b_ih, whh_a, whh_b, b_hh, out, t,
            lastT ? hdst : nullptr, lastT ? cdst : nullptr);
    }
}

// round 6
// speedup vs baseline: 1.1242x; 1.1242x over previous
#include <cuda_runtime.h>

#define BATCH 4096
#define TSEQ  20
#define INSZ  512
#define HSZ   512
#define RNK   20
#define G4    2048
#define NB    64          // batch rows per block
#define JT    128         // j columns per block
#define HSTRD 130         // ht row stride (even -> float2 stores OK, 2-way col conflict)

// Scratch (no allocations allowed -> device globals)
__device__ float g_u[BATCH * TSEQ * RNK];      // [b][t][r] input projection
__device__ float g_c[BATCH * HSZ];             // cell state, tiled [(bc*4+jt)][bb][jjl]
__device__ float g_hu[2][4 * BATCH * RNK];     // [parity][jt][b][r] h@whh_a partials

typedef unsigned long long ull;

__device__ __forceinline__ void ffma2(ull &d, ull a, ull b) {
    asm("fma.rn.f32x2 %0, %1, %2, %0;" : "+l"(d) : "l"(a), "l"(b));
}
__device__ __forceinline__ ull add2(ull a, ull b) {
    ull d; asm("add.rn.f32x2 %0, %1, %2;" : "=l"(d) : "l"(a), "l"(b)); return d;
}
__device__ __forceinline__ ull pack2(float x, float y) {
    ull r; asm("mov.b64 %0, {%1, %2};" : "=l"(r) : "f"(x), "f"(y)); return r;
}
__device__ __forceinline__ float2 unpack2(ull v) {
    float2 f; asm("mov.b64 {%0, %1}, %2;" : "=f"(f.x), "=f"(f.y) : "l"(v)); return f;
}
__device__ __forceinline__ float tanha(float x) {
    float y; asm("tanh.approx.f32 %0, %1;" : "=f"(y) : "f"(x)); return y;
}
__device__ __forceinline__ float siga(float x) {
    return fmaf(tanha(0.5f * x), 0.5f, 0.5f);
}

// ---------------------------------------------------------------------------
__global__ void kInit() {
    const int n1 = BATCH * HSZ;
    const int n2 = 4 * BATCH * RNK;
    const int stride = gridDim.x * blockDim.x;
    for (int i = blockIdx.x * blockDim.x + threadIdx.x; i < n1; i += stride) g_c[i] = 0.f;
    for (int i = blockIdx.x * blockDim.x + threadIdx.x; i < n2; i += stride) g_hu[0][i] = 0.f;
}

// ---------------------------------------------------------------------------
__global__ __launch_bounds__(256) void kPre(const float* __restrict__ x,
                                            const float* __restrict__ wa) {
    __shared__ __align__(16) float was[INSZ * RNK];
    for (int idx = threadIdx.x; idx < INSZ * RNK; idx += blockDim.x) was[idx] = wa[idx];
    __syncthreads();

    const int row = blockIdx.x * blockDim.x + threadIdx.x;
    const float4* xr = reinterpret_cast<const float4*>(x + (long)row * INSZ);

    ull acc[10];
#pragma unroll
    for (int q = 0; q < 10; q++) acc[q] = 0ull;

#pragma unroll 4
    for (int k4 = 0; k4 < INSZ / 4; k4++) {
        float4 xv = xr[k4];
#pragma unroll
        for (int i = 0; i < 4; i++) {
            float kv = (i == 0) ? xv.x : (i == 1) ? xv.y : (i == 2) ? xv.z : xv.w;
            ull ks = pack2(kv, kv);
            const ulonglong2* w2 = reinterpret_cast<const ulonglong2*>(was + (k4 * 4 + i) * RNK);
#pragma unroll
            for (int q = 0; q < 5; q++) {
                ulonglong2 wv = w2[q];
                ffma2(acc[2 * q + 0], ks, wv.x);
                ffma2(acc[2 * q + 1], ks, wv.y);
            }
        }
    }
    float* up = g_u + (long)row * RNK;
#pragma unroll
    for (int q = 0; q < 10; q++) {
        float2 f = unpack2(acc[q]);
        up[2 * q + 0] = f.x;
        up[2 * q + 1] = f.y;
    }
}

// ---------------------------------------------------------------------------
// smem partition (floats)
#define WT_OFF   0
#define WT_SZ    (40 * 512)                 // 20480  wT[k][gate*128+jjl]; reused for hu partials
#define VS_OFF   (WT_OFF + WT_SZ)
#define VS_SZ    (40 * NB * 2)              // 5120   vsplat[k][bb] as ull
#define BS_OFF   (VS_OFF + VS_SZ)
#define BS_SZ    512                        // bias [gate][jjl]
#define HT_OFF   (BS_OFF + BS_SZ)
#define HT_SZ    (NB * HSTRD)               // 8320
#define WA_OFF   (HT_OFF + HT_SZ)
#define WA_SZ    (JT * RNK)                 // 2560   wa[j][r]
#define SMEM_FLOATS (WA_OFF + WA_SZ)        // 36992 floats = 147968 B

__global__ __launch_bounds__(512, 1) void kStep(
    const float* __restrict__ wih_b, const float* __restrict__ b_ih,
    const float* __restrict__ whh_a, const float* __restrict__ whh_b,
    const float* __restrict__ b_hh,
    float* __restrict__ out, int t,
    float* __restrict__ hdst, float* __restrict__ cdst) {

    extern __shared__ __align__(16) float sm[];
    float* wT  = sm + WT_OFF;
    ull*   vsp = reinterpret_cast<ull*>(sm + VS_OFF);
    float* bs  = sm + BS_OFF;
    float* ht  = sm + HT_OFF;
    float* wa  = sm + WA_OFF;

    const int tid = threadIdx.x;
    const int jt = blockIdx.x, bc = blockIdx.y;
    const int j0 = jt * JT, b0 = bc * NB;
    const int mtile = tid & 63, ntile = tid >> 6;     // 64 x 8 thread grid
    const int jjl0 = mtile * 2, bb0 = ntile * 8;
    const long ctile = (long)(bc * 4 + jt) * (NB * JT);

    const float* rd = g_hu[t & 1];
    float*       wr = g_hu[(t + 1) & 1];

    // ---- prefetch this thread's c cells early ----
    float2 creg[8];
#pragma unroll
    for (int n = 0; n < 8; n++)
        creg[n] = *reinterpret_cast<const float2*>(g_c + ctile + (bb0 + n) * JT + jjl0);

    // ---- stage wT[k][gate*128 + jjl] : pure float4 copy, no transpose ----
#pragma unroll
    for (int it = 0; it < 10; it++) {
        int idx4 = it * 512 + tid;          // float4 index in [0, 5120)
        int r = idx4 >> 7;                  // 0..39
        int q = idx4 & 127;                 // float4 within 512-float row
        int gate = q >> 5, jjl4 = q & 31;
        const float* src = (r < RNK) ? (wih_b + r * G4) : (whh_b + (r - RNK) * G4);
        float4 v = reinterpret_cast<const float4*>(src + gate * 512 + j0)[jjl4];
        reinterpret_cast<float4*>(wT + r * 512 + gate * 128)[jjl4] = v;
    }
    // ---- bias [gate][jjl] ----
    {
        int gate = tid >> 7, jjl = tid & 127;
        int col = gate * 512 + j0 + jjl;
        bs[tid] = b_ih[col] + b_hh[col];
    }
    // ---- wa[j][r] = whh_a[(j0+j)][r] : straight float4 copy ----
    for (int idx = tid; idx < (JT * RNK) / 4; idx += 512)
        reinterpret_cast<float4*>(wa)[idx] =
            reinterpret_cast<const float4*>(whh_a + j0 * RNK)[idx];
    // ---- v = [u_t | sum of 4 hu partials], stored pre-splatted ----
    for (int idx = tid; idx < NB * 40; idx += 512) {
        int bb = idx / 40, r = idx % 40;
        int b = b0 + bb;
        float v;
        if (r < RNK) {
            v = g_u[b * (TSEQ * RNK) + t * RNK + r];
        } else {
            int off = b * RNK + (r - RNK);
            v = rd[off] + rd[BATCH * RNK + off]
              + rd[2 * BATCH * RNK + off] + rd[3 * BATCH * RNK + off];
        }
        vsp[r * NB + bb] = pack2(v, v);
    }
    __syncthreads();

    // ---- main GEMM: acc[gate][n] = f32x2 over (jjl0, jjl0+1), bias folded in ----
    ull acc[4][8];
#pragma unroll
    for (int g = 0; g < 4; g++) {
        ull bg = *reinterpret_cast<const ull*>(bs + g * 128 + jjl0);
#pragma unroll
        for (int n = 0; n < 8; n++) acc[g][n] = bg;
    }

#pragma unroll 8
    for (int k = 0; k < 40; k++) {
        ull wg[4];
#pragma unroll
        for (int g = 0; g < 4; g++)
            wg[g] = *reinterpret_cast<const ull*>(wT + k * 512 + g * 128 + jjl0);
        const ulonglong2* vrow = reinterpret_cast<const ulonglong2*>(vsp + k * NB + bb0);
        ulonglong2 v0 = vrow[0], v1 = vrow[1], v2 = vrow[2], v3 = vrow[3];
        ull vn[8] = {v0.x, v0.y, v1.x, v1.y, v2.x, v2.y, v3.x, v3.y};
#pragma unroll
        for (int g = 0; g < 4; g++)
#pragma unroll
            for (int n = 0; n < 8; n++)
                ffma2(acc[g][n], wg[g], vn[n]);
    }

    // ---- epilogue: full cell update in-thread (MUFU.TANH activations) ----
    const bool last = (hdst != nullptr);
#pragma unroll
    for (int n = 0; n < 8; n++) {
        int bb = bb0 + n;
        int b = b0 + bb;
        float2 i2 = unpack2(acc[0][n]);
        float2 f2 = unpack2(acc[1][n]);
        float2 g2 = unpack2(acc[2][n]);
        float2 o2 = unpack2(acc[3][n]);
        float2 cold = creg[n];
        float2 cc, hh;
        cc.x = fmaf(siga(f2.x), cold.x, siga(i2.x) * tanha(g2.x));
        cc.y = fmaf(siga(f2.y), cold.y, siga(i2.y) * tanha(g2.y));
        hh.x = siga(o2.x) * tanha(cc.x);
        hh.y = siga(o2.y) * tanha(cc.y);
        *reinterpret_cast<float2*>(g_c + ctile + bb * JT + jjl0) = cc;
        *reinterpret_cast<float2*>(out + ((long)b * TSEQ + t) * HSZ + j0 + jjl0) = hh;
        *reinterpret_cast<float2*>(ht + bb * HSTRD + jjl0) = hh;
        if (last) {
            *reinterpret_cast<float2*>(hdst + (long)b * HSZ + j0 + jjl0) = hh;
            *reinterpret_cast<float2*>(cdst + (long)b * HSZ + j0 + jjl0) = cc;
        }
    }
    __syncthreads();

    // ---- hu partials: thread (js, bb) accumulates ALL 20 r over 16 j ----
    // partial layout (reusing wT region): part[(rp*8+js)*64 + bb] as ull
    {
        ull* part = reinterpret_cast<ull*>(wT);
        const int js = tid >> 6, bb = tid & 63;
        ull a10[10];
#pragma unroll
        for (int rp = 0; rp < 10; rp++) a10[rp] = 0ull;
        const int jbeg = js * 16;
#pragma unroll
        for (int jj = 0; jj < 16; jj++) {
            int j = jbeg + jj;
            float hv = ht[bb * HSTRD + j];
            ull hs2 = pack2(hv, hv);
            const ulonglong2* war = reinterpret_cast<const ulonglong2*>(wa + j * RNK);
            ulonglong2 w0 = war[0], w1 = war[1], w2 = war[2], w3 = war[3], w4 = war[4];
            ffma2(a10[0], hs2, w0.x); ffma2(a10[1], hs2, w0.y);
            ffma2(a10[2], hs2, w1.x); ffma2(a10[3], hs2, w1.y);
            ffma2(a10[4], hs2, w2.x); ffma2(a10[5], hs2, w2.y);
            ffma2(a10[6], hs2, w3.x); ffma2(a10[7], hs2, w3.y);
            ffma2(a10[8], hs2, w4.x); ffma2(a10[9], hs2, w4.y);
        }
#pragma unroll
        for (int rp = 0; rp < 10; rp++)
            part[(rp * 8 + js) * 64 + bb] = a10[rp];
    }
    __syncthreads();

    // ---- reduce 8 jslices, write hu to global ----
    {
        const ull* part = reinterpret_cast<const ull*>(wT);
#pragma unroll
        for (int o = tid; o < NB * 10; o += 512) {
            int bb = o & 63, rp = o >> 6;
            ull s = part[(rp * 8 + 0) * 64 + bb];
#pragma unroll
            for (int js = 1; js < 8; js++)
                s = add2(s, part[(rp * 8 + js) * 64 + bb]);
            float2 f = unpack2(s);
            *reinterpret_cast<float2*>(
                wr + jt * (BATCH * RNK) + (b0 + bb) * RNK + 2 * rp) = f;
        }
    }
}

// ---------------------------------------------------------------------------
extern "C" void kernel_launch(void* const* d_in, const int* in_sizes, int n_in,
                              void* d_out, int out_size) {
    const float* x     = (const float*)d_in[0];
    const float* wih_a = (const float*)d_in[1];
    const float* wih_b = (const float*)d_in[2];
    const float* b_ih  = (const float*)d_in[3];
    const float* whh_a = (const float*)d_in[4];
    const float* whh_b = (const float*)d_in[5];
    const float* b_hh  = (const float*)d_in[6];
    float* out = (float*)d_out;

    const long BTH = (long)BATCH * TSEQ * HSZ;
    float* hdst = nullptr;
    float* cdst = nullptr;
    if ((long)out_size >= BTH + 2L * BATCH * HSZ) {
        hdst = out + BTH;
        cdst = hdst + (long)BATCH * HSZ;
    }

    cudaFuncSetAttribute(kStep, cudaFuncAttributeMaxDynamicSharedMemorySize,
                         SMEM_FLOATS * 4);

    kInit<<<512, 512>>>();
    kPre<<<(BATCH * TSEQ) / 256, 256>>>(x, wih_a);
    for (int t = 0; t < TSEQ; t++) {
        bool lastT = (t == TSEQ - 1);
        kStep<<<dim3(4, 64), 512, SMEM_FLOATS * 4>>>(
            wih_b, b_ih, whh_a, whh_b, b_hh, out, t,
            lastT ? hdst : nullptr, lastT ? cdst : nullptr);
    }
}